// round 1
// baseline (speedup 1.0000x reference)
#include <cuda_runtime.h>
#include <cstdint>

// hashNerf: 2D multires hash encode (L=16, T=2^18, F=2) + MLP 32->64->64->64->3
// fp32 throughout; MLP uses Blackwell packed fma.rn.f32x2 (2 FMAs/lane/instr).

#define LVL   16
#define TSZ   262144
#define TMASK 0x3FFFFu
#define NTHREADS 128

// floor(float32(16 * (64^(1/15))^l)) for l = 0..15, precomputed in double.
#define N_TAB {16.f,21.f,27.f,36.f,48.f,64.f,84.f,111.f,147.f,194.f,256.f,337.f,445.f,588.f,776.f,1024.f}

// ---- packed f32x2 helpers (sm_100+) ----
__device__ __forceinline__ unsigned long long pack2(float lo, float hi) {
    unsigned long long r;
    asm("mov.b64 %0, {%1, %2};" : "=l"(r) : "f"(lo), "f"(hi));
    return r;
}
__device__ __forceinline__ void unpack2(unsigned long long v, float& lo, float& hi) {
    asm("mov.b64 {%0, %1}, %2;" : "=f"(lo), "=f"(hi) : "l"(v));
}
__device__ __forceinline__ void fma2(unsigned long long& d, unsigned long long a, unsigned long long b) {
    asm("fma.rn.f32x2 %0, %1, %2, %0;" : "+l"(d) : "l"(a), "l"(b));
}

// Dense layer: IN -> 64 with leaky_relu(0.01). Weights row-major [IN][64] in smem,
// read as ulonglong2 (LDS.128 = two packed f32x2 operands, broadcast across warp).
template <int IN>
__device__ __forceinline__ void dense64_lrelu(const float* __restrict__ hin,
                                              const float* __restrict__ sW,
                                              const float* __restrict__ sb,
                                              float* __restrict__ hout) {
    unsigned long long acc[32];
#pragma unroll
    for (int j = 0; j < 32; j++) acc[j] = pack2(sb[2 * j], sb[2 * j + 1]);
#pragma unroll
    for (int k = 0; k < IN; k++) {
        unsigned long long a = pack2(hin[k], hin[k]);
        const ulonglong2* row = (const ulonglong2*)(sW + k * 64);
#pragma unroll
        for (int q = 0; q < 16; q++) {
            ulonglong2 w = row[q];
            fma2(acc[2 * q],     a, w.x);
            fma2(acc[2 * q + 1], a, w.y);
        }
    }
#pragma unroll
    for (int j = 0; j < 32; j++) {
        float lo, hi;
        unpack2(acc[j], lo, hi);
        hout[2 * j]     = (lo >= 0.f) ? lo : 0.01f * lo;
        hout[2 * j + 1] = (hi >= 0.f) ? hi : 0.01f * hi;
    }
}

__global__ __launch_bounds__(NTHREADS, 2)
void hash_nerf_kernel(const float* __restrict__ X,
                      const float* __restrict__ tab,
                      const float* __restrict__ W1, const float* __restrict__ b1,
                      const float* __restrict__ W2, const float* __restrict__ b2,
                      const float* __restrict__ W3, const float* __restrict__ b3,
                      const float* __restrict__ W4, const float* __restrict__ b4,
                      float* __restrict__ out, int n) {
    // smem weight cache: W1[2048] b1[64] W2[4096] b2[64] W3[4096] b3[64] W4[192] b4[3]
    __shared__ float s[10640];
    float* sW1 = s;
    float* sb1 = s + 2048;
    float* sW2 = s + 2112;
    float* sb2 = s + 6208;
    float* sW3 = s + 6272;
    float* sb3 = s + 10368;
    float* sW4 = s + 10432;
    float* sb4 = s + 10624;

    const int t = threadIdx.x;
    for (int i = t; i < 2048; i += NTHREADS) sW1[i] = W1[i];
    for (int i = t; i < 4096; i += NTHREADS) { sW2[i] = W2[i]; sW3[i] = W3[i]; }
    if (t < 64) { sb1[t] = b1[t]; sb2[t] = b2[t]; sb3[t] = b3[t]; }
    for (int i = t; i < 192; i += NTHREADS) sW4[i] = W4[i];
    if (t < 3) sb4[t] = b4[t];
    __syncthreads();

    const int idx = blockIdx.x * NTHREADS + t;
    if (idx >= n) return;

    const float x = X[2 * idx];
    const float y = X[2 * idx + 1];

    // ---- hash encode ----
    const float Ntab[16] = N_TAB;
    float feat[32];
#pragma unroll
    for (int l = 0; l < LVL; l++) {
        float xs = x * Ntab[l];
        float ys = y * Ntab[l];
        float xf = floorf(xs);
        float yf = floorf(ys);
        unsigned xi = (unsigned)xf;            // <= 1024 < 2^18
        unsigned yi = (unsigned)yf;
        // reference corners: (0,0), (0,y), (x,0), (x,y); hash = (cx*1 ^ cy*p) mod 2^18
        unsigned hy = (yi * 2654435761u) & TMASK;
        unsigned hx = xi;                       // already < 2^18
        unsigned hxy = hx ^ hy;

        const float2* tl = (const float2*)tab + (size_t)l * TSZ;
        float2 v0 = __ldg(tl);          // hash 0 (corner (0,0))
        float2 v1 = __ldg(tl + hy);
        float2 v2 = __ldg(tl + hx);
        float2 v3 = __ldg(tl + hxy);

        float fx = xs - xf, fy = ys - yf;
        float cx = 1.f - fx, cy = 1.f - fy;
        float w0 = cx * cy, w1 = cx * fy, w2 = fx * cy, w3 = fx * fy;
        feat[2 * l]     = w0 * v0.x + w1 * v1.x + w2 * v2.x + w3 * v3.x;
        feat[2 * l + 1] = w0 * v0.y + w1 * v1.y + w2 * v2.y + w3 * v3.y;
    }

    // ---- MLP ----
    float ha[64], hb[64];
    dense64_lrelu<32>(feat, sW1, sb1, ha);
    dense64_lrelu<64>(ha,   sW2, sb2, hb);
    dense64_lrelu<64>(hb,   sW3, sb3, ha);

    float o0 = sb4[0], o1 = sb4[1], o2 = sb4[2];
#pragma unroll
    for (int k = 0; k < 64; k++) {
        float hk = ha[k];
        o0 = fmaf(hk, sW4[k * 3 + 0], o0);
        o1 = fmaf(hk, sW4[k * 3 + 1], o1);
        o2 = fmaf(hk, sW4[k * 3 + 2], o2);
    }
    out[3 * idx + 0] = fmaxf(o0, 0.f);
    out[3 * idx + 1] = fmaxf(o1, 0.f);
    out[3 * idx + 2] = fmaxf(o2, 0.f);
}

extern "C" void kernel_launch(void* const* d_in, const int* in_sizes, int n_in,
                              void* d_out, int out_size) {
    const float* X   = (const float*)d_in[0];
    const float* tab = (const float*)d_in[1];
    const float* W1  = (const float*)d_in[2];
    const float* b1  = (const float*)d_in[3];
    const float* W2  = (const float*)d_in[4];
    const float* b2  = (const float*)d_in[5];
    const float* W3  = (const float*)d_in[6];
    const float* b3  = (const float*)d_in[7];
    const float* W4  = (const float*)d_in[8];
    const float* b4  = (const float*)d_in[9];
    float* out = (float*)d_out;

    int n = in_sizes[0] / 2;
    int blocks = (n + NTHREADS - 1) / NTHREADS;
    hash_nerf_kernel<<<blocks, NTHREADS>>>(X, tab, W1, b1, W2, b2, W3, b3, W4, b4, out, n);
}

// round 4
// speedup vs baseline: 4.1748x; 4.1748x over previous
#include <cuda_runtime.h>
#include <cuda_fp16.h>
#include <cstdint>

// hashNerf on sm_103 (plain target): fp32 hash encode + MLP via mma.sync m16n8k16
// f16 HMMA with fp32 accumulate; activations chained in register fragments.

#define LVL   16
#define TSZ   262144
#define TMASK 0x3FFFFu
#define THREADS 128
#define N_TAB {16.f,21.f,27.f,36.f,48.f,64.f,84.f,111.f,147.f,194.f,256.f,337.f,445.f,588.f,776.f,1024.f}

#define WPAD 72          // weight row stride in halves (144B -> conflict-free ldmatrix)
#define FPAD 40          // feature row stride in halves (80B)
// padded f16 weight image offsets (in halves)
#define OFF_W1 0
#define OFF_W2 2304      // 32*72
#define OFF_W3 6912      // 2304 + 64*72
#define OFF_W4 11520     // 6912 + 64*72
#define IMG_HALVES 12032 // + 64*8

__device__ __align__(16) unsigned short g_prepW[IMG_HALVES];

// ---------- helpers ----------
__device__ __forceinline__ uint32_t smem_u32(const void* p) {
    uint32_t a;
    asm("{ .reg .u64 t; cvta.to.shared.u64 t, %1; cvt.u32.u64 %0, t; }" : "=r"(a) : "l"(p));
    return a;
}
__device__ __forceinline__ uint32_t pack_h2(float lo, float hi) {
    uint32_t r;
    asm("cvt.rn.f16x2.f32 %0, %1, %2;" : "=r"(r) : "f"(hi), "f"(lo));
    return r;
}
__device__ __forceinline__ void ldsm_x4(uint32_t& r0, uint32_t& r1, uint32_t& r2, uint32_t& r3, uint32_t addr) {
    asm volatile("ldmatrix.sync.aligned.m8n8.x4.shared.b16 {%0,%1,%2,%3}, [%4];"
                 : "=r"(r0), "=r"(r1), "=r"(r2), "=r"(r3) : "r"(addr));
}
__device__ __forceinline__ void ldsm_x4_t(uint32_t& r0, uint32_t& r1, uint32_t& r2, uint32_t& r3, uint32_t addr) {
    asm volatile("ldmatrix.sync.aligned.m8n8.x4.trans.shared.b16 {%0,%1,%2,%3}, [%4];"
                 : "=r"(r0), "=r"(r1), "=r"(r2), "=r"(r3) : "r"(addr));
}
__device__ __forceinline__ void ldsm_x2_t(uint32_t& r0, uint32_t& r1, uint32_t addr) {
    asm volatile("ldmatrix.sync.aligned.m8n8.x2.trans.shared.b16 {%0,%1}, [%2];"
                 : "=r"(r0), "=r"(r1) : "r"(addr));
}
__device__ __forceinline__ void mma16816(float* c, const uint32_t* a, uint32_t b0, uint32_t b1) {
    asm volatile("mma.sync.aligned.m16n8k16.row.col.f32.f16.f16.f32 "
                 "{%0,%1,%2,%3}, {%4,%5,%6,%7}, {%8,%9}, {%0,%1,%2,%3};"
                 : "+f"(c[0]), "+f"(c[1]), "+f"(c[2]), "+f"(c[3])
                 : "r"(a[0]), "r"(a[1]), "r"(a[2]), "r"(a[3]), "r"(b0), "r"(b1));
}
__device__ __forceinline__ float lrelu(float v) { return (v >= 0.f) ? v : 0.01f * v; }

// ---------- prep: convert weights to f16 padded image ----------
__global__ void prep_kernel(const float* __restrict__ W1, const float* __restrict__ W2,
                            const float* __restrict__ W3, const float* __restrict__ W4) {
    __half* img = (__half*)g_prepW;
    for (int i = threadIdx.x; i < IMG_HALVES; i += blockDim.x) img[i] = __float2half(0.f);
    __syncthreads();
    for (int i = threadIdx.x; i < 32 * 64; i += blockDim.x)
        img[OFF_W1 + (i >> 6) * WPAD + (i & 63)] = __float2half(W1[i]);
    for (int i = threadIdx.x; i < 64 * 64; i += blockDim.x) {
        img[OFF_W2 + (i >> 6) * WPAD + (i & 63)] = __float2half(W2[i]);
        img[OFF_W3 + (i >> 6) * WPAD + (i & 63)] = __float2half(W3[i]);
    }
    for (int i = threadIdx.x; i < 64 * 3; i += blockDim.x)
        img[OFF_W4 + (i / 3) * 8 + (i % 3)] = __float2half(W4[i]);
}

// ---------- main kernel ----------
__global__ void __launch_bounds__(THREADS)
hash_nerf_mma(const float* __restrict__ X, const float* __restrict__ tab,
              const float* __restrict__ b1, const float* __restrict__ b2,
              const float* __restrict__ b3, const float* __restrict__ b4,
              float* __restrict__ out, int n) {
    __shared__ __align__(16) unsigned short sW[IMG_HALVES];      // 24064 B
    __shared__ __align__(16) unsigned short sF[4][32 * FPAD];    // 10240 B
    __shared__ float sb[3][64];
    __shared__ float sb4[8];

    const int tid  = threadIdx.x;
    const int warp = tid >> 5;
    const int lane = tid & 31;

    // stage weights (pre-converted) + biases
    {
        const uint4* src = (const uint4*)g_prepW;
        uint4* dst = (uint4*)sW;
        for (int i = tid; i < IMG_HALVES / 8; i += THREADS) dst[i] = src[i];
    }
    if (tid < 64) { sb[0][tid] = b1[tid]; sb[1][tid] = b2[tid]; sb[2][tid] = b3[tid]; }
    if (tid < 8) sb4[tid] = (tid < 3) ? b4[tid] : 0.f;
    __syncthreads();

    // ---- hash encode (fp32, one thread = one point) ----
    const int pbase = blockIdx.x * THREADS + warp * 32;  // warp's first point
    const int pt = pbase + lane;
    const float Ntab[16] = N_TAB;
    float feat[32];
    if (pt < n) {
        const float x = X[2 * pt];
        const float y = X[2 * pt + 1];
#pragma unroll
        for (int l = 0; l < LVL; l++) {
            float xs = x * Ntab[l], ys = y * Ntab[l];
            float xf = floorf(xs), yf = floorf(ys);
            unsigned xi = (unsigned)xf, yi = (unsigned)yf;
            unsigned hy = (yi * 2654435761u) & TMASK;
            unsigned hx = xi;                 // < 2^18 already
            unsigned hxy = hx ^ hy;
            const float2* tl = (const float2*)tab + (size_t)l * TSZ;
            float2 v0 = __ldg(tl);
            float2 v1 = __ldg(tl + hy);
            float2 v2 = __ldg(tl + hx);
            float2 v3 = __ldg(tl + hxy);
            float fx = xs - xf, fy = ys - yf;
            float cx = 1.f - fx, cy = 1.f - fy;
            float w0 = cx * cy, w1 = cx * fy, w2 = fx * cy, w3 = fx * fy;
            feat[2 * l]     = w0 * v0.x + w1 * v1.x + w2 * v2.x + w3 * v3.x;
            feat[2 * l + 1] = w0 * v0.y + w1 * v1.y + w2 * v2.y + w3 * v3.y;
        }
    } else {
#pragma unroll
        for (int i = 0; i < 32; i++) feat[i] = 0.f;
    }

    // write features (f16) to this warp's staging rows
    {
        uint32_t* frow = (uint32_t*)(sF[warp] + lane * FPAD);
#pragma unroll
        for (int i = 0; i < 16; i++) frow[i] = pack_h2(feat[2 * i], feat[2 * i + 1]);
    }
    __syncwarp();

    const uint32_t uW = smem_u32(sW);
    const uint32_t uF = smem_u32(sF[warp]);
    const int l15 = lane & 15;
    const int lhi = (lane >> 4) << 3;       // +8 halves for upper half-warp
    const int tg2 = (lane & 3) << 1;        // accumulator column pair base
    const int g   = lane >> 2;              // accumulator row base

    // A fragments: a[mtile][ktile][4]
    uint32_t a[2][4][4];
#pragma unroll
    for (int mt = 0; mt < 2; mt++)
#pragma unroll
        for (int kt = 0; kt < 2; kt++) {
            uint32_t ad = uF + (uint32_t)(((mt * 16 + l15) * FPAD + kt * 16 + lhi) * 2);
            ldsm_x4(a[mt][kt][0], a[mt][kt][1], a[mt][kt][2], a[mt][kt][3], ad);
        }

    const uint32_t woffs[3] = {OFF_W1 * 2u, OFF_W2 * 2u, OFF_W3 * 2u};
    const int nkts[3] = {2, 4, 4};

#pragma unroll 1
    for (int layer = 0; layer < 3; layer++) {
        const uint32_t wb = uW + woffs[layer];
        const int nkt = nkts[layer];
        float c[2][8][4];
#pragma unroll
        for (int mt = 0; mt < 2; mt++)
#pragma unroll
            for (int nt = 0; nt < 8; nt++) {
                float v0 = sb[layer][8 * nt + tg2];
                float v1 = sb[layer][8 * nt + tg2 + 1];
                c[mt][nt][0] = v0; c[mt][nt][1] = v1;
                c[mt][nt][2] = v0; c[mt][nt][3] = v1;
            }
#pragma unroll
        for (int kt = 0; kt < 4; kt++) {
            if (kt >= nkt) break;
#pragma unroll
            for (int n2 = 0; n2 < 4; n2++) {
                uint32_t b0, b1, b2, b3;
                uint32_t bd = wb + (uint32_t)(((kt * 16 + l15) * WPAD + n2 * 16 + lhi) * 2);
                ldsm_x4_t(b0, b1, b2, b3, bd);
#pragma unroll
                for (int mt = 0; mt < 2; mt++) {
                    mma16816(c[mt][2 * n2],     a[mt][kt], b0, b1);
                    mma16816(c[mt][2 * n2 + 1], a[mt][kt], b2, b3);
                }
            }
        }
        // leaky-relu + repack accumulators as next-layer A fragments
#pragma unroll
        for (int mt = 0; mt < 2; mt++)
#pragma unroll
            for (int j = 0; j < 4; j++) {
                a[mt][j][0] = pack_h2(lrelu(c[mt][2 * j][0]),     lrelu(c[mt][2 * j][1]));
                a[mt][j][1] = pack_h2(lrelu(c[mt][2 * j][2]),     lrelu(c[mt][2 * j][3]));
                a[mt][j][2] = pack_h2(lrelu(c[mt][2 * j + 1][0]), lrelu(c[mt][2 * j + 1][1]));
                a[mt][j][3] = pack_h2(lrelu(c[mt][2 * j + 1][2]), lrelu(c[mt][2 * j + 1][3]));
            }
    }

    // ---- layer 4: 64 -> 3 (single n8 tile, cols 3..7 are zero-padded) ----
    float c4[2][4];
#pragma unroll
    for (int mt = 0; mt < 2; mt++) {
        c4[mt][0] = sb4[tg2]; c4[mt][1] = sb4[tg2 + 1];
        c4[mt][2] = sb4[tg2]; c4[mt][3] = sb4[tg2 + 1];
    }
#pragma unroll
    for (int kt = 0; kt < 4; kt++) {
        uint32_t b0, b1;
        uint32_t bd = uW + OFF_W4 * 2u + (uint32_t)(((kt * 16 + l15) * 8) * 2);
        ldsm_x2_t(b0, b1, bd);
#pragma unroll
        for (int mt = 0; mt < 2; mt++) mma16816(c4[mt], a[mt][kt], b0, b1);
    }

    // relu + predicated stores: rows (g, g+8) per m-tile, cols (tg2, tg2+1)
#pragma unroll
    for (int mt = 0; mt < 2; mt++) {
        int p0 = pbase + mt * 16 + g;
        int p1 = p0 + 8;
        float v0 = fmaxf(c4[mt][0], 0.f), v1 = fmaxf(c4[mt][1], 0.f);
        float v2 = fmaxf(c4[mt][2], 0.f), v3 = fmaxf(c4[mt][3], 0.f);
        if (tg2 < 3) {
            if (p0 < n) out[3 * p0 + tg2] = v0;
            if (p1 < n) out[3 * p1 + tg2] = v2;
        }
        if (tg2 + 1 < 3) {
            if (p0 < n) out[3 * p0 + tg2 + 1] = v1;
            if (p1 < n) out[3 * p1 + tg2 + 1] = v3;
        }
    }
}

extern "C" void kernel_launch(void* const* d_in, const int* in_sizes, int n_in,
                              void* d_out, int out_size) {
    const float* X   = (const float*)d_in[0];
    const float* tab = (const float*)d_in[1];
    const float* W1  = (const float*)d_in[2];
    const float* b1  = (const float*)d_in[3];
    const float* W2  = (const float*)d_in[4];
    const float* b2  = (const float*)d_in[5];
    const float* W3  = (const float*)d_in[6];
    const float* b3  = (const float*)d_in[7];
    const float* W4  = (const float*)d_in[8];
    const float* b4  = (const float*)d_in[9];
    float* out = (float*)d_out;

    int n = in_sizes[0] / 2;
    prep_kernel<<<1, 256>>>(W1, W2, W3, W4);
    int blocks = (n + THREADS - 1) / THREADS;
    hash_nerf_mma<<<blocks, THREADS>>>(X, tab, b1, b2, b3, b4, out, n);
}